// round 14
// baseline (speedup 1.0000x reference)
#include <cuda_runtime.h>
#include <cuda_bf16.h>
#include <math.h>
#include <stdint.h>

#define SEQ    2048
#define HID    4096
#define NHEADS 32
#define NKV    8
#define HD     128
#define QD     (NHEADS*HD)    // 4096
#define KVD    (NKV*HD)       // 1024
#define QKVD   (QD + 2*KVD)   // 6144

// Scratch (allocation-free rule: __device__ globals)
__device__ float g_qkv[(size_t)SEQ*QKVD];      // fused q|k|v fp32
__device__ float g_bqkv[QKVD];                 // fused bias

// Split activations (bf16 hi/lo)
__device__ __nv_bfloat16 g_h_hi[(size_t)SEQ*HID], g_h_lo[(size_t)SEQ*HID];
__device__ __nv_bfloat16 g_a_hi[(size_t)SEQ*QD],  g_a_lo[(size_t)SEQ*QD];

// Split q/k after rope (q pre-scaled by 1/sqrt(HD)), and V transposed+split
__device__ __nv_bfloat16 g_q_hi[(size_t)SEQ*QD],  g_q_lo[(size_t)SEQ*QD];
__device__ __nv_bfloat16 g_k_hi[(size_t)SEQ*KVD], g_k_lo[(size_t)SEQ*KVD];
__device__ __nv_bfloat16 g_vt_hi[(size_t)KVD*SEQ], g_vt_lo[(size_t)KVD*SEQ];

// Split-transposed weights: Wt[n][k] bf16 hi/lo (K-major for mma B operand)
__device__ __nv_bfloat16 g_wqkv_hi[(size_t)QKVD*HID], g_wqkv_lo[(size_t)QKVD*HID];
__device__ __nv_bfloat16 g_wo_hi[(size_t)HID*QD],  g_wo_lo[(size_t)HID*QD];

// ---------------------------------------------------------------------------
// Helpers (baseline PTX only: mma.sync / ldmatrix / cp.async)
// ---------------------------------------------------------------------------
__device__ __forceinline__ uint32_t smem_u32(const void* p) {
    uint32_t a;
    asm("{ .reg .u64 t; cvta.to.shared.u64 t, %1; cvt.u32.u64 %0, t; }" : "=r"(a) : "l"(p));
    return a;
}

__device__ __forceinline__ void mma_bf16(float* d, const uint32_t* a, const uint32_t* b) {
    asm volatile("mma.sync.aligned.m16n8k16.row.col.f32.bf16.bf16.f32 "
                 "{%0,%1,%2,%3}, {%4,%5,%6,%7}, {%8,%9}, {%0,%1,%2,%3};"
                 : "+f"(d[0]), "+f"(d[1]), "+f"(d[2]), "+f"(d[3])
                 : "r"(a[0]), "r"(a[1]), "r"(a[2]), "r"(a[3]),
                   "r"(b[0]), "r"(b[1]));
}

__device__ __forceinline__ void ldsm4(uint32_t* r, uint32_t addr) {
    asm volatile("ldmatrix.sync.aligned.m8n8.x4.shared.b16 {%0,%1,%2,%3}, [%4];"
                 : "=r"(r[0]), "=r"(r[1]), "=r"(r[2]), "=r"(r[3]) : "r"(addr));
}

#define CP_ASYNC(dst, src) asm volatile("cp.async.cg.shared.global [%0], [%1], 16;" :: "r"(dst), "l"(src))
#define CP_COMMIT()        asm volatile("cp.async.commit_group;" ::: "memory")
#define CP_WAIT(n)         asm volatile("cp.async.wait_group %0;" :: "n"(n) : "memory")

__device__ __forceinline__ uint32_t pack2(__nv_bfloat16 a, __nv_bfloat16 b) {
    return ((uint32_t)__bfloat16_as_ushort(b) << 16) | (uint32_t)__bfloat16_as_ushort(a);
}
__device__ __forceinline__ void split1(float x, __nv_bfloat16& h, __nv_bfloat16& l) {
    h = __float2bfloat16(x);
    l = __float2bfloat16(x - __bfloat162float(h));
}

// swizzled offset inside a [rows x k16chunks] bf16 tile (chunk block = rows*32B)
__device__ __forceinline__ uint32_t swz_off(int chunkstride, int c, int row, int half) {
    return (uint32_t)(c * chunkstride + row * 32 + ((half ^ ((row >> 2) & 1) ^ (c & 1)) << 4));
}

// ---------------------------------------------------------------------------
// Weight/V transpose + split: W[K][N] (row stride ldW) fp32 -> Thi/Tlo[N][K] bf16
// ---------------------------------------------------------------------------
__global__ __launch_bounds__(256)
void transpose_split(const float* __restrict__ W,
                     __nv_bfloat16* __restrict__ Thi, __nv_bfloat16* __restrict__ Tlo,
                     int K, int N, int ldW)
{
    __shared__ float ts[32][33];
    const int tx = threadIdx.x & 31;
    const int ty = threadIdx.x >> 5;            // 0..7
    const int k0 = blockIdx.y * 32;
    const int n0 = blockIdx.x * 32;

#pragma unroll
    for (int r = 0; r < 4; r++) {
        int kr = ty + r * 8;
        ts[kr][tx] = W[(size_t)(k0 + kr) * ldW + n0 + tx];
    }
    __syncthreads();
#pragma unroll
    for (int r = 0; r < 4; r++) {
        int nl = ty + r * 8;
        float x = ts[tx][nl];
        __nv_bfloat16 h, l;
        split1(x, h, l);
        size_t off = (size_t)(n0 + nl) * K + k0 + tx;
        Thi[off] = h;
        Tlo[off] = l;
    }
}

// ---------------------------------------------------------------------------
// Activation split + bias concat
// ---------------------------------------------------------------------------
__global__ __launch_bounds__(256)
void split_f32(const float* __restrict__ X,
               __nv_bfloat16* __restrict__ Hi, __nv_bfloat16* __restrict__ Lo, int n4)
{
    int idx = blockIdx.x * 256 + threadIdx.x;
    if (idx < n4) {
        float4 v = ((const float4*)X)[idx];
        __nv_bfloat16 h0,h1,h2,h3,l0,l1,l2,l3;
        split1(v.x,h0,l0); split1(v.y,h1,l1); split1(v.z,h2,l2); split1(v.w,h3,l3);
        ((uint2*)Hi)[idx] = make_uint2(pack2(h0,h1), pack2(h2,h3));
        ((uint2*)Lo)[idx] = make_uint2(pack2(l0,l1), pack2(l2,l3));
    }
}

__global__ __launch_bounds__(256)
void concat_bias(const float* __restrict__ bq, const float* __restrict__ bk,
                 const float* __restrict__ bv, float* __restrict__ out)
{
    int i = blockIdx.x * 256 + threadIdx.x;
    if (i < QD) out[i] = bq[i];
    else if (i < QD + KVD) out[i] = bk[i - QD];
    else if (i < QKVD) out[i] = bv[i - QD - KVD];
}

// ---------------------------------------------------------------------------
// bf16-split tensor-core GEMM, 3-stage cp.async pipeline.
// 128 threads, 4 warps (2m x 2n), warp tile 64x64 -> ldsm:mma 1:6.
// Block 128x128, BK=32. Stage = Ahi|Alo|Bhi|Blo 8KB each = 32KB; NST=3.
// 2 CTAs/SM (96KB smem, <=256 regs/thread within 64K RF).
// ---------------------------------------------------------------------------
#define NST 3
#define GEMM_SMEM (NST * 32768)

#define ISSUE_TILE(t) do {                                                     \
    uint32_t stg_ = sb + (uint32_t)(((t) % NST) << 15);                        \
    int k0_ = (t) * 32;                                                        \
    _Pragma("unroll")                                                          \
    for (int i_ = 0; i_ < 4; i_++) {                                           \
        int m_ = tid;                                                          \
        int c_ = i_ >> 1, h_ = i_ & 1;                                         \
        uint32_t dst_ = stg_ + c_*4096 + m_*32 +                               \
                        (uint32_t)((h_ ^ ((m_>>2)&1) ^ c_) << 4);              \
        size_t sa_ = (size_t)(bm + m_) * K + k0_ + c_*16 + h_*8;               \
        size_t sb2_ = (size_t)(bn + m_) * K + k0_ + c_*16 + h_*8;              \
        CP_ASYNC(dst_,         Ahi + sa_);                                     \
        CP_ASYNC(dst_ + 8192,  Alo + sa_);                                     \
        CP_ASYNC(dst_ + 16384, Bhi + sb2_);                                    \
        CP_ASYNC(dst_ + 24576, Blo + sb2_);                                    \
    }                                                                          \
    CP_COMMIT();                                                               \
} while (0)

__global__ __launch_bounds__(128, 2)
void gemm_bf16(const __nv_bfloat16* __restrict__ Ahi, const __nv_bfloat16* __restrict__ Alo,
               const __nv_bfloat16* __restrict__ Bhi, const __nv_bfloat16* __restrict__ Blo,
               const float* __restrict__ bias, float* __restrict__ C,
               int M, int N, int K)
{
    extern __shared__ char smem[];
    const uint32_t sb = smem_u32(smem);
    const int tid  = threadIdx.x;
    const int warp = tid >> 5;
    const int lane = tid & 31;
    const int bm = blockIdx.y * 128;
    const int bn = blockIdx.x * 128;
    const int wm = (warp & 1) * 64;
    const int wn = (warp >> 1) * 64;

    float acc[4][8][4];
#pragma unroll
    for (int mt = 0; mt < 4; mt++)
#pragma unroll
        for (int nt = 0; nt < 8; nt++)
#pragma unroll
            for (int e = 0; e < 4; e++) acc[mt][nt][e] = 0.f;

    const int nT = K / 32;

    ISSUE_TILE(0);
    ISSUE_TILE(1);

    const int mrow  = wm + (lane & 15);
    const int ahalf = lane >> 4;
    const int noff  = (lane & 7) + ((lane >> 4) & 1) * 8;
    const int bhalf = (lane >> 3) & 1;

    for (int t = 0; t < nT; t++) {
        if (t + 1 < nT) { CP_WAIT(1); } else { CP_WAIT(0); }
        __syncthreads();
        if (t + 2 < nT) ISSUE_TILE(t + 2);

        const uint32_t stg = sb + (uint32_t)((t % NST) << 15);

#pragma unroll
        for (int c = 0; c < 2; c++) {
            uint32_t bh[8][2], bl[8][2];
#pragma unroll
            for (int p = 0; p < 4; p++) {
                int n = wn + p * 16 + noff;
                uint32_t bd = stg + 16384 + c*4096 + n*32 +
                              (uint32_t)((bhalf ^ ((n>>2)&1) ^ c) << 4);
                uint32_t r[4];
                ldsm4(r, bd);
                bh[2*p][0]=r[0]; bh[2*p][1]=r[1]; bh[2*p+1][0]=r[2]; bh[2*p+1][1]=r[3];
                ldsm4(r, bd + 8192);
                bl[2*p][0]=r[0]; bl[2*p][1]=r[1]; bl[2*p+1][0]=r[2]; bl[2*p+1][1]=r[3];
            }
            uint32_t a[4][4];
#pragma unroll
            for (int mt = 0; mt < 4; mt++) {
                int m = mrow + mt * 16;
                ldsm4(a[mt], stg + c*4096 + m*32 +
                             (uint32_t)((ahalf ^ ((m>>2)&1) ^ c) << 4));
            }
#pragma unroll
            for (int mt = 0; mt < 4; mt++)
#pragma unroll
                for (int nt = 0; nt < 8; nt++) {
                    mma_bf16(acc[mt][nt], a[mt], bh[nt]);
                    mma_bf16(acc[mt][nt], a[mt], bl[nt]);
                }
#pragma unroll
            for (int mt = 0; mt < 4; mt++) {
                int m = mrow + mt * 16;
                ldsm4(a[mt], stg + c*4096 + m*32 +
                             (uint32_t)((ahalf ^ ((m>>2)&1) ^ c) << 4) + 8192);
            }
#pragma unroll
            for (int mt = 0; mt < 4; mt++)
#pragma unroll
                for (int nt = 0; nt < 8; nt++)
                    mma_bf16(acc[mt][nt], a[mt], bh[nt]);
        }
    }

    const int g = lane >> 2, tig = lane & 3;
#pragma unroll
    for (int mt = 0; mt < 4; mt++) {
        int row = bm + wm + mt * 16 + g;
#pragma unroll
        for (int nt = 0; nt < 8; nt++) {
            int col = bn + wn + nt * 8 + tig * 2;
            float b0 = bias[col], b1 = bias[col + 1];
            float2 v0 = make_float2(acc[mt][nt][0] + b0, acc[mt][nt][1] + b1);
            float2 v1 = make_float2(acc[mt][nt][2] + b0, acc[mt][nt][3] + b1);
            *(float2*)(C + (size_t)row * N + col)       = v0;
            *(float2*)(C + (size_t)(row + 8) * N + col) = v1;
        }
    }
}

// ---------------------------------------------------------------------------
// RoPE: reads fused fp32 qkv, writes SPLIT bf16 q (pre-scaled) and k.
// ---------------------------------------------------------------------------
__global__ void rope_kernel(const float* __restrict__ qkv, const int* __restrict__ pos_ids,
                            __nv_bfloat16* __restrict__ qhi, __nv_bfloat16* __restrict__ qlo,
                            __nv_bfloat16* __restrict__ khi, __nv_bfloat16* __restrict__ klo)
{
    int s = blockIdx.x;
    int i = threadIdx.x;                // 0..63
    int pos = pos_ids[s];
    const float scale = 0.08838834764831845f;  // 1/sqrt(128)

    double invf = exp(-(double)i * (log(10000.0) / 64.0));
    float ang = (float)((double)pos * invf);
    float sn, cs;
    sincosf(ang, &sn, &cs);

    const float* qb = qkv + (size_t)s * QKVD;
#pragma unroll
    for (int h = 0; h < NHEADS; h++) {
        float x = qb[h * HD + i];
        float y = qb[h * HD + i + 64];
        float q0 = (x * cs - y * sn) * scale;
        float q1 = (y * cs + x * sn) * scale;
        __nv_bfloat16 h0, l0, h1, l1;
        split1(q0, h0, l0); split1(q1, h1, l1);
        size_t o = (size_t)s * QD + h * HD + i;
        qhi[o] = h0; qlo[o] = l0;
        qhi[o + 64] = h1; qlo[o + 64] = l1;
    }
    const float* kb = qkv + (size_t)s * QKVD + QD;
#pragma unroll
    for (int h = 0; h < NKV; h++) {
        float x = kb[h * HD + i];
        float y = kb[h * HD + i + 64];
        float k0 = x * cs - y * sn;
        float k1 = y * cs + x * sn;
        __nv_bfloat16 h0, l0, h1, l1;
        split1(k0, h0, l0); split1(k1, h1, l1);
        size_t o = (size_t)s * KVD + h * HD + i;
        khi[o] = h0; klo[o] = l0;
        khi[o + 64] = h1; klo[o + 64] = l1;
    }
}

// ---------------------------------------------------------------------------
// Tensor-core causal flash attention (bf16 3-term split, online softmax).
// CTA = (qt 64-row tile, head). 128 threads, 4 warps (2m x 2n).
// P tile aliased into K region. qt runs DESCENDING for wave balance.
// ---------------------------------------------------------------------------
#define AS_Q    0
#define AS_K    32768
#define AS_V    65536
#define AS_ST   98304
#define ATTN_SMEM (98304 + 1024)

__global__ __launch_bounds__(128)
void attn_tc(const __nv_bfloat16* __restrict__ qhi, const __nv_bfloat16* __restrict__ qlo,
             const __nv_bfloat16* __restrict__ khi, const __nv_bfloat16* __restrict__ klo,
             const __nv_bfloat16* __restrict__ vthi, const __nv_bfloat16* __restrict__ vtlo,
             __nv_bfloat16* __restrict__ ohi, __nv_bfloat16* __restrict__ olo)
{
    extern __shared__ char smem[];
    const uint32_t sb = smem_u32(smem);
    float* sm_max = (float*)(smem + AS_ST);        // [2][64]
    float* sm_sum = (float*)(smem + AS_ST + 512);  // [2][64]

    const int tid  = threadIdx.x;
    const int warp = tid >> 5;
    const int lane = tid & 31;
    const int g    = lane >> 2;
    const int tig  = lane & 3;
    const int wm   = (warp & 1) * 32;      // S/O row group
    const int wn   = (warp >> 1) * 32;     // S col group
    const int wno  = (warp >> 1) * 64;     // O col group
    const int wnid = warp >> 1;
    const int qt   = gridDim.x - 1 - blockIdx.x;   // heavy tiles first
    const int h    = blockIdx.y;
    const int kvh  = h >> 2;

    // ---- load Q tile (64 x 128, hi/lo) via cp.async, swizzled ----
    {
        const __nv_bfloat16* qh_g = qhi + (size_t)(qt*64) * QD + h * HD;
        const __nv_bfloat16* ql_g = qlo + (size_t)(qt*64) * QD + h * HD;
#pragma unroll
        for (int i = 0; i < 16; i++) {
            int u = tid + i * 128;           // 0..2047
            int arr = u >> 10;               // 0: hi, 1: lo
            int v = u & 1023;
            int row = v >> 4, c = (v >> 1) & 7, hf = v & 1;
            uint32_t dst = sb + AS_Q + arr * 16384 + swz_off(2048, c, row, hf);
            const __nv_bfloat16* src = (arr ? ql_g : qh_g) + (size_t)row * QD + c * 16 + hf * 8;
            CP_ASYNC(dst, src);
        }
        CP_COMMIT();
    }

    float o_acc[2][8][4];
#pragma unroll
    for (int mt = 0; mt < 2; mt++)
#pragma unroll
        for (int nt = 0; nt < 8; nt++)
#pragma unroll
            for (int e = 0; e < 4; e++) o_acc[mt][nt][e] = 0.f;

    float m_row[2][2], l_row[2][2], corr[2][2];
#pragma unroll
    for (int mt = 0; mt < 2; mt++)
#pragma unroll
        for (int rh = 0; rh < 2; rh++) { m_row[mt][rh] = -INFINITY; l_row[mt][rh] = 0.f; }

    for (int kt = 0; kt <= qt; kt++) {
        // ---- issue K group, then V group ----
        {
            const __nv_bfloat16* kh_g = khi + (size_t)(kt*64) * KVD + kvh * HD;
            const __nv_bfloat16* kl_g = klo + (size_t)(kt*64) * KVD + kvh * HD;
#pragma unroll
            for (int i = 0; i < 16; i++) {
                int u = tid + i * 128;
                int arr = u >> 10;
                int v = u & 1023;
                int row = v >> 4, c = (v >> 1) & 7, hf = v & 1;
                uint32_t dst = sb + AS_K + arr * 16384 + swz_off(2048, c, row, hf);
                const __nv_bfloat16* src = (arr ? kl_g : kh_g) + (size_t)row * KVD + c * 16 + hf * 8;
                CP_ASYNC(dst, src);
            }
            CP_COMMIT();
            const __nv_bfloat16* vh_g = vthi + (size_t)(kvh * HD) * SEQ + kt * 64;
            const __nv_bfloat16* vl_g = vtlo + (size_t)(kvh * HD) * SEQ + kt * 64;
#pragma unroll
            for (int i = 0; i < 16; i++) {
                int u = tid + i * 128;
                int arr = u >> 10;
                int v = u & 1023;
                int row = v >> 3, c = (v >> 1) & 3, hf = v & 1;
                uint32_t dst = sb + AS_V + arr * 16384 + swz_off(4096, c, row, hf);
                const __nv_bfloat16* src = (arr ? vl_g : vh_g) + (size_t)row * SEQ + c * 16 + hf * 8;
                CP_ASYNC(dst, src);
            }
            CP_COMMIT();
        }
        CP_WAIT(1);          // Q (first iter) + K arrived; V may be in flight
        __syncthreads();

        // ---- S = Q @ K^T (3-term) ----
        float s_acc[2][4][4];
#pragma unroll
        for (int mt = 0; mt < 2; mt++)
#pragma unroll
            for (int nt = 0; nt < 4; nt++)
#pragma unroll
                for (int e = 0; e < 4; e++) s_acc[mt][nt][e] = 0.f;

#pragma unroll
        for (int c = 0; c < 8; c++) {
            uint32_t ah[2][4], al[2][4];
            {
                const int mrow = wm + (lane & 15);
                const int hf = lane >> 4;
#pragma unroll
                for (int mt = 0; mt < 2; mt++) {
                    int m = mrow + mt * 16;
                    uint32_t ad = sb + AS_Q + swz_off(2048, c, m, hf);
                    ldsm4(ah[mt], ad);
                    ldsm4(al[mt], ad + 16384);
                }
            }
            uint32_t bh[4][2], bl[4][2];
            {
                const int noff = (lane & 7) + ((lane >> 4) & 1) * 8;
                const int hf = (lane >> 3) & 1;
#pragma unroll
                for (int p = 0; p < 2; p++) {
                    int n = wn + p * 16 + noff;
                    uint32_t bd = sb + AS_K + swz_off(2048, c, n, hf);
                    uint32_t r[4];
                    ldsm4(r, bd);
                    bh[2*p][0]=r[0]; bh[2*p][1]=r[1]; bh[2*p+1][0]=r[2]; bh[2*p+1][1]=r[3];
                    ldsm4(r, bd + 16384);
                    bl[2*p][0]=r[0]; bl[2*p][1]=r[1]; bl[2*p+1][0]=r[2]; bl[2*p+1][1]=r[3];
                }
            }
#pragma unroll
            for (int mt = 0; mt < 2; mt++)
#pragma unroll
                for (int nt = 0; nt < 4; nt++) {
                    mma_bf16(s_acc[mt][nt], ah[mt], bh[nt]);
                    mma_bf16(s_acc[mt][nt], ah[mt], bl[nt]);
                    mma_bf16(s_acc[mt][nt], al[mt], bh[nt]);
                }
        }

        // ---- causal mask (diag tile) ----
        if (kt == qt) {
#pragma unroll
            for (int mt = 0; mt < 2; mt++)
#pragma unroll
                for (int nt = 0; nt < 4; nt++)
#pragma unroll
                    for (int e = 0; e < 4; e++) {
                        int r = wm + mt * 16 + g + (e >> 1) * 8;
                        int cc = wn + nt * 8 + tig * 2 + (e & 1);
                        if (cc > r) s_acc[mt][nt][e] = -1e30f;
                    }
        }

        // ---- row max: quad reduce + cross-warp via smem ----
#pragma unroll
        for (int mt = 0; mt < 2; mt++)
#pragma unroll
            for (int rh = 0; rh < 2; rh++) {
                float pm = -1e30f;
#pragma unroll
                for (int nt = 0; nt < 4; nt++)
                    pm = fmaxf(pm, fmaxf(s_acc[mt][nt][2*rh], s_acc[mt][nt][2*rh+1]));
                pm = fmaxf(pm, __shfl_xor_sync(0xffffffff, pm, 1));
                pm = fmaxf(pm, __shfl_xor_sync(0xffffffff, pm, 2));
                if (tig == 0) sm_max[wnid * 64 + wm + mt * 16 + g + rh * 8] = pm;
            }
        __syncthreads();   // also: all S reads of K done -> P may overwrite K region

        // ---- exp, P store (split, aliased into K region), O rescale, partials ----
        float rs[2][2] = {{0.f, 0.f}, {0.f, 0.f}};
#pragma unroll
        for (int mt = 0; mt < 2; mt++)
#pragma unroll
            for (int rh = 0; rh < 2; rh++) {
                int r = wm + mt * 16 + g + rh * 8;
                float tm = fmaxf(sm_max[r], sm_max[64 + r]);
                float mn = fmaxf(m_row[mt][rh], tm);
                corr[mt][rh] = __expf(m_row[mt][rh] - mn);
                m_row[mt][rh] = mn;
            }
#pragma unroll
        for (int mt = 0; mt < 2; mt++) {
            int r0 = wm + mt * 16 + g;
#pragma unroll
            for (int nt = 0; nt < 4; nt++) {
                float p0 = __expf(s_acc[mt][nt][0] - m_row[mt][0]);
                float p1 = __expf(s_acc[mt][nt][1] - m_row[mt][0]);
                float p2 = __expf(s_acc[mt][nt][2] - m_row[mt][1]);
                float p3 = __expf(s_acc[mt][nt][3] - m_row[mt][1]);
                rs[mt][0] += p0 + p1;
                rs[mt][1] += p2 + p3;
                __nv_bfloat16 h0,l0,h1,l1,h2,l2,h3,l3;
                split1(p0,h0,l0); split1(p1,h1,l1); split1(p2,h2,l2); split1(p3,h3,l3);
                int chk = wnid * 2 + (nt >> 1);
                int hf  = nt & 1;
                uint32_t a0 = sb + AS_K + (uint32_t)(chk * 2048 +
                              ((hf ^ ((r0 >> 2) & 1) ^ (chk & 1)) << 4) + tig * 4 + r0 * 32);
                asm volatile("st.shared.b32 [%0], %1;" :: "r"(a0), "r"(pack2(h0,h1)));
                asm volatile("st.shared.b32 [%0], %1;" :: "r"(a0 + 8192), "r"(pack2(l0,l1)));
                asm volatile("st.shared.b32 [%0], %1;" :: "r"(a0 + 256), "r"(pack2(h2,h3)));
                asm volatile("st.shared.b32 [%0], %1;" :: "r"(a0 + 256 + 8192), "r"(pack2(l2,l3)));
            }
        }
#pragma unroll
        for (int mt = 0; mt < 2; mt++)
#pragma unroll
            for (int nt = 0; nt < 8; nt++) {
                o_acc[mt][nt][0] *= corr[mt][0];
                o_acc[mt][nt][1] *= corr[mt][0];
                o_acc[mt][nt][2] *= corr[mt][1];
                o_acc[mt][nt][3] *= corr[mt][1];
            }
#pragma unroll
        for (int mt = 0; mt < 2; mt++)
#pragma unroll
            for (int rh = 0; rh < 2; rh++) {
                float v = rs[mt][rh];
                v += __shfl_xor_sync(0xffffffff, v, 1);
                v += __shfl_xor_sync(0xffffffff, v, 2);
                if (tig == 0) sm_sum[wnid * 64 + wm + mt * 16 + g + rh * 8] = v;
            }
        CP_WAIT(0);        // V arrived (own groups); barrier below publishes all
        __syncthreads();

#pragma unroll
        for (int mt = 0; mt < 2; mt++)
#pragma unroll
            for (int rh = 0; rh < 2; rh++) {
                int r = wm + mt * 16 + g + rh * 8;
                l_row[mt][rh] = l_row[mt][rh] * corr[mt][rh] + sm_sum[r] + sm_sum[64 + r];
            }

        // ---- O += P @ Vt (3-term; P read from aliased K region) ----
#pragma unroll
        for (int c = 0; c < 4; c++) {
            uint32_t ph[2][4], pl[2][4];
            {
                const int mrow = wm + (lane & 15);
                const int hf = lane >> 4;
#pragma unroll
                for (int mt = 0; mt < 2; mt++) {
                    int m = mrow + mt * 16;
                    uint32_t ad = sb + AS_K + swz_off(2048, c, m, hf);
                    ldsm4(ph[mt], ad);
                    ldsm4(pl[mt], ad + 8192);
                }
            }
            uint32_t vh[8][2], vl[8][2];
            {
                const int noff = (lane & 7) + ((lane >> 4) & 1) * 8;
                const int hf = (lane >> 3) & 1;
#pragma unroll
                for (int p = 0; p < 4; p++) {
                    int n = wno + p * 16 + noff;
                    uint32_t bd = sb + AS_V + swz_off(4096, c, n, hf);
                    uint32_t r[4];
                    ldsm4(r, bd);
                    vh[2*p][0]=r[0]; vh[2*p][1]=r[1]; vh[2*p+1][0]=r[2]; vh[2*p+1][1]=r[3];
                    ldsm4(r, bd + 16384);
                    vl[2*p][0]=r[0]; vl[2*p][1]=r[1]; vl[2*p+1][0]=r[2]; vl[2*p+1][1]=r[3];
                }
            }
#pragma unroll
            for (int mt = 0; mt < 2; mt++)
#pragma unroll
                for (int nt = 0; nt < 8; nt++) {
                    mma_bf16(o_acc[mt][nt], ph[mt], vh[nt]);
                    mma_bf16(o_acc[mt][nt], ph[mt], vl[nt]);
                    mma_bf16(o_acc[mt][nt], pl[mt], vh[nt]);
                }
        }
        __syncthreads();
    }

    // ---- normalize + store split bf16 (feeds O-projection) ----
#pragma unroll
    for (int mt = 0; mt < 2; mt++) {
        float inv0 = 1.f / l_row[mt][0];
        float inv1 = 1.f / l_row[mt][1];
        int r = qt * 64 + wm + mt * 16 + g;
#pragma unroll
        for (int nt = 0; nt < 8; nt++) {
            int col = h * HD + wno + nt * 8 + tig * 2;
            float v0 = o_acc[mt][nt][0] * inv0, v1 = o_acc[mt][nt][1] * inv0;
            float v2 = o_acc[mt][nt][2] * inv1, v3 = o_acc[mt][nt][3] * inv1;
            __nv_bfloat16 h0,l0,h1,l1,h2,l2,h3,l3;
            split1(v0,h0,l0); split1(v1,h1,l1); split1(v2,h2,l2); split1(v3,h3,l3);
            *(uint32_t*)(ohi + (size_t)r * QD + col)       = pack2(h0,h1);
            *(uint32_t*)(olo + (size_t)r * QD + col)       = pack2(l0,l1);
            *(uint32_t*)(ohi + (size_t)(r + 8) * QD + col) = pack2(h2,h3);
            *(uint32_t*)(olo + (size_t)(r + 8) * QD + col) = pack2(l2,l3);
        }
    }
}

// ---------------------------------------------------------------------------
// Launch
// ---------------------------------------------------------------------------
extern "C" void kernel_launch(void* const* d_in, const int* in_sizes, int n_in,
                              void* d_out, int out_size)
{
    const float* hidden = (const float*)d_in[0];
    // d_in[1] = attention_mask: all-True by construction; causality applied exactly.
    const int*   pos_ids = (const int*)d_in[2];
    const float* Wq = (const float*)d_in[3];
    const float* bq = (const float*)d_in[4];
    const float* Wk = (const float*)d_in[5];
    const float* bk = (const float*)d_in[6];
    const float* Wv = (const float*)d_in[7];
    const float* bv = (const float*)d_in[8];
    const float* Wo = (const float*)d_in[9];
    const float* bo = (const float*)d_in[10];
    float* out = (float*)d_out;

    float *pqkv, *pbqkv;
    __nv_bfloat16 *hh, *hl, *ah, *al;
    __nv_bfloat16 *qh, *ql, *kh, *kl, *vth, *vtl;
    __nv_bfloat16 *wqkvh, *wqkvl, *woh, *wol;
    cudaGetSymbolAddress((void**)&pqkv, g_qkv);
    cudaGetSymbolAddress((void**)&pbqkv, g_bqkv);
    cudaGetSymbolAddress((void**)&hh, g_h_hi);  cudaGetSymbolAddress((void**)&hl, g_h_lo);
    cudaGetSymbolAddress((void**)&ah, g_a_hi);  cudaGetSymbolAddress((void**)&al, g_a_lo);
    cudaGetSymbolAddress((void**)&qh, g_q_hi);  cudaGetSymbolAddress((void**)&ql, g_q_lo);
    cudaGetSymbolAddress((void**)&kh, g_k_hi);  cudaGetSymbolAddress((void**)&kl, g_k_lo);
    cudaGetSymbolAddress((void**)&vth, g_vt_hi); cudaGetSymbolAddress((void**)&vtl, g_vt_lo);
    cudaGetSymbolAddress((void**)&wqkvh, g_wqkv_hi); cudaGetSymbolAddress((void**)&wqkvl, g_wqkv_lo);
    cudaGetSymbolAddress((void**)&woh, g_wo_hi); cudaGetSymbolAddress((void**)&wol, g_wo_lo);

    cudaFuncSetAttribute(gemm_bf16, cudaFuncAttributeMaxDynamicSharedMemorySize, GEMM_SMEM);
    cudaFuncSetAttribute(attn_tc,  cudaFuncAttributeMaxDynamicSharedMemorySize, ATTN_SMEM);

    dim3 blk(256);

    // Weight transpose + bf16 split into fused [q|k|v] buffer, plus Wo
    transpose_split<<<dim3(QD/32,  HID/32), blk>>>(Wq, wqkvh, wqkvl, HID, QD, QD);
    transpose_split<<<dim3(KVD/32, HID/32), blk>>>(Wk, wqkvh + (size_t)QD*HID,
                                                   wqkvl + (size_t)QD*HID, HID, KVD, KVD);
    transpose_split<<<dim3(KVD/32, HID/32), blk>>>(Wv, wqkvh + (size_t)(QD+KVD)*HID,
                                                   wqkvl + (size_t)(QD+KVD)*HID, HID, KVD, KVD);
    transpose_split<<<dim3(QD/32,  HID/32), blk>>>(Wo, woh, wol, QD, HID, HID);
    concat_bias<<<QKVD/256, blk>>>(bq, bk, bv, pbqkv);

    // Activation split for fused QKV projection
    split_f32<<<(SEQ*HID/4 + 255)/256, blk>>>(hidden, hh, hl, SEQ*HID/4);

    // Fused QKV projection (one N=6144 GEMM)
    gemm_bf16<<<dim3(QKVD/128, SEQ/128), 128, GEMM_SMEM>>>(hh, hl, wqkvh, wqkvl,
                                                           pbqkv, pqkv, SEQ, QKVD, HID);

    // V transpose+split: V[s][n] (stride QKVD) -> Vt[n][s] hi/lo
    transpose_split<<<dim3(KVD/32, SEQ/32), blk>>>(pqkv + QD + KVD, vth, vtl, SEQ, KVD, QKVD);

    // RoPE -> split bf16 q (scaled) / k
    rope_kernel<<<SEQ, 64>>>(pqkv, pos_ids, qh, ql, kh, kl);

    // Tensor-core causal flash attention (writes split bf16 directly)
    attn_tc<<<dim3(SEQ/64, NHEADS), 128, ATTN_SMEM>>>(qh, ql, kh, kl, vth, vtl, ah, al);

    // Output projection
    gemm_bf16<<<dim3(HID/128, SEQ/128), 128, GEMM_SMEM>>>(ah, al, woh, wol, bo, out, SEQ, HID, QD);
}

// round 16
// speedup vs baseline: 1.0446x; 1.0446x over previous
#include <cuda_runtime.h>
#include <cuda_bf16.h>
#include <math.h>
#include <stdint.h>

#define SEQ    2048
#define HID    4096
#define NHEADS 32
#define NKV    8
#define HD     128
#define QD     (NHEADS*HD)    // 4096
#define KVD    (NKV*HD)       // 1024
#define QKVD   (QD + 2*KVD)   // 6144

// Scratch (allocation-free rule: __device__ globals)
__device__ float g_qkv[(size_t)SEQ*QKVD];      // fused q|k|v fp32
__device__ float g_bqkv[QKVD];                 // fused bias

// Split activations (bf16 hi/lo)
__device__ __nv_bfloat16 g_h_hi[(size_t)SEQ*HID], g_h_lo[(size_t)SEQ*HID];
__device__ __nv_bfloat16 g_a_hi[(size_t)SEQ*QD],  g_a_lo[(size_t)SEQ*QD];

// Split q/k after rope (q pre-scaled by 1/sqrt(HD)), and V transposed+split
__device__ __nv_bfloat16 g_q_hi[(size_t)SEQ*QD],  g_q_lo[(size_t)SEQ*QD];
__device__ __nv_bfloat16 g_k_hi[(size_t)SEQ*KVD], g_k_lo[(size_t)SEQ*KVD];
__device__ __nv_bfloat16 g_vt_hi[(size_t)KVD*SEQ], g_vt_lo[(size_t)KVD*SEQ];

// Split-transposed weights: Wt[n][k] bf16 hi/lo (K-major for mma B operand)
__device__ __nv_bfloat16 g_wqkv_hi[(size_t)QKVD*HID], g_wqkv_lo[(size_t)QKVD*HID];
__device__ __nv_bfloat16 g_wo_hi[(size_t)HID*QD],  g_wo_lo[(size_t)HID*QD];

// ---------------------------------------------------------------------------
// Helpers (baseline PTX only: mma.sync / ldmatrix / cp.async)
// ---------------------------------------------------------------------------
__device__ __forceinline__ uint32_t smem_u32(const void* p) {
    uint32_t a;
    asm("{ .reg .u64 t; cvta.to.shared.u64 t, %1; cvt.u32.u64 %0, t; }" : "=r"(a) : "l"(p));
    return a;
}

__device__ __forceinline__ void mma_bf16(float* d, const uint32_t* a, const uint32_t* b) {
    asm volatile("mma.sync.aligned.m16n8k16.row.col.f32.bf16.bf16.f32 "
                 "{%0,%1,%2,%3}, {%4,%5,%6,%7}, {%8,%9}, {%0,%1,%2,%3};"
                 : "+f"(d[0]), "+f"(d[1]), "+f"(d[2]), "+f"(d[3])
                 : "r"(a[0]), "r"(a[1]), "r"(a[2]), "r"(a[3]),
                   "r"(b[0]), "r"(b[1]));
}

__device__ __forceinline__ void ldsm4(uint32_t* r, uint32_t addr) {
    asm volatile("ldmatrix.sync.aligned.m8n8.x4.shared.b16 {%0,%1,%2,%3}, [%4];"
                 : "=r"(r[0]), "=r"(r[1]), "=r"(r[2]), "=r"(r[3]) : "r"(addr));
}

#define CP_ASYNC(dst, src) asm volatile("cp.async.cg.shared.global [%0], [%1], 16;" :: "r"(dst), "l"(src))
#define CP_COMMIT()        asm volatile("cp.async.commit_group;" ::: "memory")
#define CP_WAIT(n)         asm volatile("cp.async.wait_group %0;" :: "n"(n) : "memory")

__device__ __forceinline__ uint32_t pack2(__nv_bfloat16 a, __nv_bfloat16 b) {
    return ((uint32_t)__bfloat16_as_ushort(b) << 16) | (uint32_t)__bfloat16_as_ushort(a);
}
__device__ __forceinline__ void split1(float x, __nv_bfloat16& h, __nv_bfloat16& l) {
    h = __float2bfloat16(x);
    l = __float2bfloat16(x - __bfloat162float(h));
}

// swizzled offset inside a [rows x k16chunks] bf16 tile (chunk block = rows*32B)
__device__ __forceinline__ uint32_t swz_off(int chunkstride, int c, int row, int half) {
    return (uint32_t)(c * chunkstride + row * 32 + ((half ^ ((row >> 2) & 1) ^ (c & 1)) << 4));
}

// ---------------------------------------------------------------------------
// Weight/V transpose + split: W[K][N] (row stride ldW) fp32 -> Thi/Tlo[N][K] bf16
// ---------------------------------------------------------------------------
__global__ __launch_bounds__(256)
void transpose_split(const float* __restrict__ W,
                     __nv_bfloat16* __restrict__ Thi, __nv_bfloat16* __restrict__ Tlo,
                     int K, int N, int ldW)
{
    __shared__ float ts[32][33];
    const int tx = threadIdx.x & 31;
    const int ty = threadIdx.x >> 5;            // 0..7
    const int k0 = blockIdx.y * 32;
    const int n0 = blockIdx.x * 32;

#pragma unroll
    for (int r = 0; r < 4; r++) {
        int kr = ty + r * 8;
        ts[kr][tx] = W[(size_t)(k0 + kr) * ldW + n0 + tx];
    }
    __syncthreads();
#pragma unroll
    for (int r = 0; r < 4; r++) {
        int nl = ty + r * 8;
        float x = ts[tx][nl];
        __nv_bfloat16 h, l;
        split1(x, h, l);
        size_t off = (size_t)(n0 + nl) * K + k0 + tx;
        Thi[off] = h;
        Tlo[off] = l;
    }
}

// ---------------------------------------------------------------------------
// Activation split + bias concat
// ---------------------------------------------------------------------------
__global__ __launch_bounds__(256)
void split_f32(const float* __restrict__ X,
               __nv_bfloat16* __restrict__ Hi, __nv_bfloat16* __restrict__ Lo, int n4)
{
    int idx = blockIdx.x * 256 + threadIdx.x;
    if (idx < n4) {
        float4 v = ((const float4*)X)[idx];
        __nv_bfloat16 h0,h1,h2,h3,l0,l1,l2,l3;
        split1(v.x,h0,l0); split1(v.y,h1,l1); split1(v.z,h2,l2); split1(v.w,h3,l3);
        ((uint2*)Hi)[idx] = make_uint2(pack2(h0,h1), pack2(h2,h3));
        ((uint2*)Lo)[idx] = make_uint2(pack2(l0,l1), pack2(l2,l3));
    }
}

__global__ __launch_bounds__(256)
void concat_bias(const float* __restrict__ bq, const float* __restrict__ bk,
                 const float* __restrict__ bv, float* __restrict__ out)
{
    int i = blockIdx.x * 256 + threadIdx.x;
    if (i < QD) out[i] = bq[i];
    else if (i < QD + KVD) out[i] = bk[i - QD];
    else if (i < QKVD) out[i] = bv[i - QD - KVD];
}

// ---------------------------------------------------------------------------
// bf16-split tensor-core GEMM, 3-stage cp.async pipeline, 2 CTAs/SM.
// C[M,N] = (Ahi+Alo)[M,K] @ (Bhi+Blo)[N,K]^T + bias (3 mma terms).
// Block 128x128, BK=32, 8 warps (2m x 4n), warp tile 64x32 (R11 config).
// Grid: blockIdx.x = M (fast) -> wave working set (A all + ~19 B blocks)
// stays L2-resident; B (weights) read from DRAM once.
// ---------------------------------------------------------------------------
#define NST 3
#define GEMM_SMEM (NST * 32768)

#define ISSUE_TILE(t) do {                                                     \
    uint32_t stg_ = sb + (uint32_t)(((t) % NST) << 15);                        \
    int k0_ = (t) * 32;                                                        \
    _Pragma("unroll")                                                          \
    for (int i_ = 0; i_ < 2; i_++) {                                           \
        int u_ = tid * 2 + i_;                                                 \
        int m_ = u_ >> 2, rem_ = u_ & 3;                                       \
        int c_ = rem_ >> 1, h_ = rem_ & 1;                                     \
        uint32_t dst_ = stg_ + c_*4096 + m_*32 +                               \
                        (uint32_t)((h_ ^ ((m_>>2)&1) ^ c_) << 4);              \
        size_t sa_ = (size_t)(bm + m_) * K + k0_ + c_*16 + h_*8;               \
        size_t sb2_ = (size_t)(bn + m_) * K + k0_ + c_*16 + h_*8;              \
        CP_ASYNC(dst_,         Ahi + sa_);                                     \
        CP_ASYNC(dst_ + 8192,  Alo + sa_);                                     \
        CP_ASYNC(dst_ + 16384, Bhi + sb2_);                                    \
        CP_ASYNC(dst_ + 24576, Blo + sb2_);                                    \
    }                                                                          \
    CP_COMMIT();                                                               \
} while (0)

__global__ __launch_bounds__(256, 2)
void gemm_bf16(const __nv_bfloat16* __restrict__ Ahi, const __nv_bfloat16* __restrict__ Alo,
               const __nv_bfloat16* __restrict__ Bhi, const __nv_bfloat16* __restrict__ Blo,
               const float* __restrict__ bias, float* __restrict__ C,
               int M, int N, int K)
{
    extern __shared__ char smem[];
    const uint32_t sb = smem_u32(smem);
    const int tid  = threadIdx.x;
    const int warp = tid >> 5;
    const int lane = tid & 31;
    const int bm = blockIdx.x * 128;    // M fast: consecutive CTAs share B in L2
    const int bn = blockIdx.y * 128;
    const int wm = (warp & 1) * 64;
    const int wn = (warp >> 1) * 32;

    float acc[4][4][4];
#pragma unroll
    for (int mt = 0; mt < 4; mt++)
#pragma unroll
        for (int nt = 0; nt < 4; nt++)
#pragma unroll
            for (int e = 0; e < 4; e++) acc[mt][nt][e] = 0.f;

    const int nT = K / 32;

    ISSUE_TILE(0);
    ISSUE_TILE(1);

    const int mrow  = wm + (lane & 15);
    const int ahalf = lane >> 4;
    const int noff  = (lane & 7) + ((lane >> 4) & 1) * 8;
    const int bhalf = (lane >> 3) & 1;

    for (int t = 0; t < nT; t++) {
        if (t + 1 < nT) { CP_WAIT(1); } else { CP_WAIT(0); }
        __syncthreads();
        if (t + 2 < nT) ISSUE_TILE(t + 2);

        const uint32_t stg = sb + (uint32_t)((t % NST) << 15);

#pragma unroll
        for (int c = 0; c < 2; c++) {
            uint32_t bh[4][2], bl[4][2];
#pragma unroll
            for (int p = 0; p < 2; p++) {
                int n = wn + p * 16 + noff;
                uint32_t bd = stg + 16384 + c*4096 + n*32 +
                              (uint32_t)((bhalf ^ ((n>>2)&1) ^ c) << 4);
                uint32_t r[4];
                ldsm4(r, bd);
                bh[2*p][0]=r[0]; bh[2*p][1]=r[1]; bh[2*p+1][0]=r[2]; bh[2*p+1][1]=r[3];
                ldsm4(r, bd + 8192);
                bl[2*p][0]=r[0]; bl[2*p][1]=r[1]; bl[2*p+1][0]=r[2]; bl[2*p+1][1]=r[3];
            }
            uint32_t a[4][4];
#pragma unroll
            for (int mt = 0; mt < 4; mt++) {
                int m = mrow + mt * 16;
                ldsm4(a[mt], stg + c*4096 + m*32 +
                             (uint32_t)((ahalf ^ ((m>>2)&1) ^ c) << 4));
            }
#pragma unroll
            for (int mt = 0; mt < 4; mt++)
#pragma unroll
                for (int nt = 0; nt < 4; nt++) {
                    mma_bf16(acc[mt][nt], a[mt], bh[nt]);
                    mma_bf16(acc[mt][nt], a[mt], bl[nt]);
                }
#pragma unroll
            for (int mt = 0; mt < 4; mt++) {
                int m = mrow + mt * 16;
                ldsm4(a[mt], stg + c*4096 + m*32 +
                             (uint32_t)((ahalf ^ ((m>>2)&1) ^ c) << 4) + 8192);
            }
#pragma unroll
            for (int mt = 0; mt < 4; mt++)
#pragma unroll
                for (int nt = 0; nt < 4; nt++)
                    mma_bf16(acc[mt][nt], a[mt], bh[nt]);
        }
    }

    const int g = lane >> 2, tig = lane & 3;
#pragma unroll
    for (int mt = 0; mt < 4; mt++) {
        int row = bm + wm + mt * 16 + g;
#pragma unroll
        for (int nt = 0; nt < 4; nt++) {
            int col = bn + wn + nt * 8 + tig * 2;
            float b0 = bias[col], b1 = bias[col + 1];
            float2 v0 = make_float2(acc[mt][nt][0] + b0, acc[mt][nt][1] + b1);
            float2 v1 = make_float2(acc[mt][nt][2] + b0, acc[mt][nt][3] + b1);
            *(float2*)(C + (size_t)row * N + col)       = v0;
            *(float2*)(C + (size_t)(row + 8) * N + col) = v1;
        }
    }
}

// ---------------------------------------------------------------------------
// RoPE: reads fused fp32 qkv, writes SPLIT bf16 q (pre-scaled) and k.
// ---------------------------------------------------------------------------
__global__ void rope_kernel(const float* __restrict__ qkv, const int* __restrict__ pos_ids,
                            __nv_bfloat16* __restrict__ qhi, __nv_bfloat16* __restrict__ qlo,
                            __nv_bfloat16* __restrict__ khi, __nv_bfloat16* __restrict__ klo)
{
    int s = blockIdx.x;
    int i = threadIdx.x;                // 0..63
    int pos = pos_ids[s];
    const float scale = 0.08838834764831845f;  // 1/sqrt(128)

    double invf = exp(-(double)i * (log(10000.0) / 64.0));
    float ang = (float)((double)pos * invf);
    float sn, cs;
    sincosf(ang, &sn, &cs);

    const float* qb = qkv + (size_t)s * QKVD;
#pragma unroll
    for (int h = 0; h < NHEADS; h++) {
        float x = qb[h * HD + i];
        float y = qb[h * HD + i + 64];
        float q0 = (x * cs - y * sn) * scale;
        float q1 = (y * cs + x * sn) * scale;
        __nv_bfloat16 h0, l0, h1, l1;
        split1(q0, h0, l0); split1(q1, h1, l1);
        size_t o = (size_t)s * QD + h * HD + i;
        qhi[o] = h0; qlo[o] = l0;
        qhi[o + 64] = h1; qlo[o + 64] = l1;
    }
    const float* kb = qkv + (size_t)s * QKVD + QD;
#pragma unroll
    for (int h = 0; h < NKV; h++) {
        float x = kb[h * HD + i];
        float y = kb[h * HD + i + 64];
        float k0 = x * cs - y * sn;
        float k1 = y * cs + x * sn;
        __nv_bfloat16 h0, l0, h1, l1;
        split1(k0, h0, l0); split1(k1, h1, l1);
        size_t o = (size_t)s * KVD + h * HD + i;
        khi[o] = h0; klo[o] = l0;
        khi[o + 64] = h1; klo[o + 64] = l1;
    }
}

// ---------------------------------------------------------------------------
// Tensor-core causal flash attention (bf16 3-term split, online softmax).
// CTA = (qt 64-row tile, head). 128 threads, 4 warps (2m x 2n).
// P tile aliased into K region. qt runs DESCENDING for wave balance.
// ---------------------------------------------------------------------------
#define AS_Q    0
#define AS_K    32768
#define AS_V    65536
#define AS_ST   98304
#define ATTN_SMEM (98304 + 1024)

__global__ __launch_bounds__(128)
void attn_tc(const __nv_bfloat16* __restrict__ qhi, const __nv_bfloat16* __restrict__ qlo,
             const __nv_bfloat16* __restrict__ khi, const __nv_bfloat16* __restrict__ klo,
             const __nv_bfloat16* __restrict__ vthi, const __nv_bfloat16* __restrict__ vtlo,
             __nv_bfloat16* __restrict__ ohi, __nv_bfloat16* __restrict__ olo)
{
    extern __shared__ char smem[];
    const uint32_t sb = smem_u32(smem);
    float* sm_max = (float*)(smem + AS_ST);        // [2][64]
    float* sm_sum = (float*)(smem + AS_ST + 512);  // [2][64]

    const int tid  = threadIdx.x;
    const int warp = tid >> 5;
    const int lane = tid & 31;
    const int g    = lane >> 2;
    const int tig  = lane & 3;
    const int wm   = (warp & 1) * 32;      // S/O row group
    const int wn   = (warp >> 1) * 32;     // S col group
    const int wno  = (warp >> 1) * 64;     // O col group
    const int wnid = warp >> 1;
    const int qt   = gridDim.x - 1 - blockIdx.x;   // heavy tiles first
    const int h    = blockIdx.y;
    const int kvh  = h >> 2;

    // ---- load Q tile (64 x 128, hi/lo) via cp.async, swizzled ----
    {
        const __nv_bfloat16* qh_g = qhi + (size_t)(qt*64) * QD + h * HD;
        const __nv_bfloat16* ql_g = qlo + (size_t)(qt*64) * QD + h * HD;
#pragma unroll
        for (int i = 0; i < 16; i++) {
            int u = tid + i * 128;           // 0..2047
            int arr = u >> 10;               // 0: hi, 1: lo
            int v = u & 1023;
            int row = v >> 4, c = (v >> 1) & 7, hf = v & 1;
            uint32_t dst = sb + AS_Q + arr * 16384 + swz_off(2048, c, row, hf);
            const __nv_bfloat16* src = (arr ? ql_g : qh_g) + (size_t)row * QD + c * 16 + hf * 8;
            CP_ASYNC(dst, src);
        }
        CP_COMMIT();
    }

    float o_acc[2][8][4];
#pragma unroll
    for (int mt = 0; mt < 2; mt++)
#pragma unroll
        for (int nt = 0; nt < 8; nt++)
#pragma unroll
            for (int e = 0; e < 4; e++) o_acc[mt][nt][e] = 0.f;

    float m_row[2][2], l_row[2][2], corr[2][2];
#pragma unroll
    for (int mt = 0; mt < 2; mt++)
#pragma unroll
        for (int rh = 0; rh < 2; rh++) { m_row[mt][rh] = -INFINITY; l_row[mt][rh] = 0.f; }

    for (int kt = 0; kt <= qt; kt++) {
        // ---- issue K group, then V group ----
        {
            const __nv_bfloat16* kh_g = khi + (size_t)(kt*64) * KVD + kvh * HD;
            const __nv_bfloat16* kl_g = klo + (size_t)(kt*64) * KVD + kvh * HD;
#pragma unroll
            for (int i = 0; i < 16; i++) {
                int u = tid + i * 128;
                int arr = u >> 10;
                int v = u & 1023;
                int row = v >> 4, c = (v >> 1) & 7, hf = v & 1;
                uint32_t dst = sb + AS_K + arr * 16384 + swz_off(2048, c, row, hf);
                const __nv_bfloat16* src = (arr ? kl_g : kh_g) + (size_t)row * KVD + c * 16 + hf * 8;
                CP_ASYNC(dst, src);
            }
            CP_COMMIT();
            const __nv_bfloat16* vh_g = vthi + (size_t)(kvh * HD) * SEQ + kt * 64;
            const __nv_bfloat16* vl_g = vtlo + (size_t)(kvh * HD) * SEQ + kt * 64;
#pragma unroll
            for (int i = 0; i < 16; i++) {
                int u = tid + i * 128;
                int arr = u >> 10;
                int v = u & 1023;
                int row = v >> 3, c = (v >> 1) & 3, hf = v & 1;
                uint32_t dst = sb + AS_V + arr * 16384 + swz_off(4096, c, row, hf);
                const __nv_bfloat16* src = (arr ? vl_g : vh_g) + (size_t)row * SEQ + c * 16 + hf * 8;
                CP_ASYNC(dst, src);
            }
            CP_COMMIT();
        }
        CP_WAIT(1);          // Q (first iter) + K arrived; V may be in flight
        __syncthreads();

        // ---- S = Q @ K^T (3-term) ----
        float s_acc[2][4][4];
#pragma unroll
        for (int mt = 0; mt < 2; mt++)
#pragma unroll
            for (int nt = 0; nt < 4; nt++)
#pragma unroll
                for (int e = 0; e < 4; e++) s_acc[mt][nt][e] = 0.f;

#pragma unroll
        for (int c = 0; c < 8; c++) {
            uint32_t ah[2][4], al[2][4];
            {
                const int mrow = wm + (lane & 15);
                const int hf = lane >> 4;
#pragma unroll
                for (int mt = 0; mt < 2; mt++) {
                    int m = mrow + mt * 16;
                    uint32_t ad = sb + AS_Q + swz_off(2048, c, m, hf);
                    ldsm4(ah[mt], ad);
                    ldsm4(al[mt], ad + 16384);
                }
            }
            uint32_t bh[4][2], bl[4][2];
            {
                const int noff = (lane & 7) + ((lane >> 4) & 1) * 8;
                const int hf = (lane >> 3) & 1;
#pragma unroll
                for (int p = 0; p < 2; p++) {
                    int n = wn + p * 16 + noff;
                    uint32_t bd = sb + AS_K + swz_off(2048, c, n, hf);
                    uint32_t r[4];
                    ldsm4(r, bd);
                    bh[2*p][0]=r[0]; bh[2*p][1]=r[1]; bh[2*p+1][0]=r[2]; bh[2*p+1][1]=r[3];
                    ldsm4(r, bd + 16384);
                    bl[2*p][0]=r[0]; bl[2*p][1]=r[1]; bl[2*p+1][0]=r[2]; bl[2*p+1][1]=r[3];
                }
            }
#pragma unroll
            for (int mt = 0; mt < 2; mt++)
#pragma unroll
                for (int nt = 0; nt < 4; nt++) {
                    mma_bf16(s_acc[mt][nt], ah[mt], bh[nt]);
                    mma_bf16(s_acc[mt][nt], ah[mt], bl[nt]);
                    mma_bf16(s_acc[mt][nt], al[mt], bh[nt]);
                }
        }

        // ---- causal mask (diag tile) ----
        if (kt == qt) {
#pragma unroll
            for (int mt = 0; mt < 2; mt++)
#pragma unroll
                for (int nt = 0; nt < 4; nt++)
#pragma unroll
                    for (int e = 0; e < 4; e++) {
                        int r = wm + mt * 16 + g + (e >> 1) * 8;
                        int cc = wn + nt * 8 + tig * 2 + (e & 1);
                        if (cc > r) s_acc[mt][nt][e] = -1e30f;
                    }
        }

        // ---- row max: quad reduce + cross-warp via smem ----
#pragma unroll
        for (int mt = 0; mt < 2; mt++)
#pragma unroll
            for (int rh = 0; rh < 2; rh++) {
                float pm = -1e30f;
#pragma unroll
                for (int nt = 0; nt < 4; nt++)
                    pm = fmaxf(pm, fmaxf(s_acc[mt][nt][2*rh], s_acc[mt][nt][2*rh+1]));
                pm = fmaxf(pm, __shfl_xor_sync(0xffffffff, pm, 1));
                pm = fmaxf(pm, __shfl_xor_sync(0xffffffff, pm, 2));
                if (tig == 0) sm_max[wnid * 64 + wm + mt * 16 + g + rh * 8] = pm;
            }
        __syncthreads();   // also: all S reads of K done -> P may overwrite K region

        // ---- exp, P store (split, aliased into K region), O rescale, partials ----
        float rs[2][2] = {{0.f, 0.f}, {0.f, 0.f}};
#pragma unroll
        for (int mt = 0; mt < 2; mt++)
#pragma unroll
            for (int rh = 0; rh < 2; rh++) {
                int r = wm + mt * 16 + g + rh * 8;
                float tm = fmaxf(sm_max[r], sm_max[64 + r]);
                float mn = fmaxf(m_row[mt][rh], tm);
                corr[mt][rh] = __expf(m_row[mt][rh] - mn);
                m_row[mt][rh] = mn;
            }
#pragma unroll
        for (int mt = 0; mt < 2; mt++) {
            int r0 = wm + mt * 16 + g;
#pragma unroll
            for (int nt = 0; nt < 4; nt++) {
                float p0 = __expf(s_acc[mt][nt][0] - m_row[mt][0]);
                float p1 = __expf(s_acc[mt][nt][1] - m_row[mt][0]);
                float p2 = __expf(s_acc[mt][nt][2] - m_row[mt][1]);
                float p3 = __expf(s_acc[mt][nt][3] - m_row[mt][1]);
                rs[mt][0] += p0 + p1;
                rs[mt][1] += p2 + p3;
                __nv_bfloat16 h0,l0,h1,l1,h2,l2,h3,l3;
                split1(p0,h0,l0); split1(p1,h1,l1); split1(p2,h2,l2); split1(p3,h3,l3);
                int chk = wnid * 2 + (nt >> 1);
                int hf  = nt & 1;
                uint32_t a0 = sb + AS_K + (uint32_t)(chk * 2048 +
                              ((hf ^ ((r0 >> 2) & 1) ^ (chk & 1)) << 4) + tig * 4 + r0 * 32);
                asm volatile("st.shared.b32 [%0], %1;" :: "r"(a0), "r"(pack2(h0,h1)));
                asm volatile("st.shared.b32 [%0], %1;" :: "r"(a0 + 8192), "r"(pack2(l0,l1)));
                asm volatile("st.shared.b32 [%0], %1;" :: "r"(a0 + 256), "r"(pack2(h2,h3)));
                asm volatile("st.shared.b32 [%0], %1;" :: "r"(a0 + 256 + 8192), "r"(pack2(l2,l3)));
            }
        }
#pragma unroll
        for (int mt = 0; mt < 2; mt++)
#pragma unroll
            for (int nt = 0; nt < 8; nt++) {
                o_acc[mt][nt][0] *= corr[mt][0];
                o_acc[mt][nt][1] *= corr[mt][0];
                o_acc[mt][nt][2] *= corr[mt][1];
                o_acc[mt][nt][3] *= corr[mt][1];
            }
#pragma unroll
        for (int mt = 0; mt < 2; mt++)
#pragma unroll
            for (int rh = 0; rh < 2; rh++) {
                float v = rs[mt][rh];
                v += __shfl_xor_sync(0xffffffff, v, 1);
                v += __shfl_xor_sync(0xffffffff, v, 2);
                if (tig == 0) sm_sum[wnid * 64 + wm + mt * 16 + g + rh * 8] = v;
            }
        CP_WAIT(0);        // V arrived (own groups); barrier below publishes all
        __syncthreads();

#pragma unroll
        for (int mt = 0; mt < 2; mt++)
#pragma unroll
            for (int rh = 0; rh < 2; rh++) {
                int r = wm + mt * 16 + g + rh * 8;
                l_row[mt][rh] = l_row[mt][rh] * corr[mt][rh] + sm_sum[r] + sm_sum[64 + r];
            }

        // ---- O += P @ Vt (3-term; P read from aliased K region) ----
#pragma unroll
        for (int c = 0; c < 4; c++) {
            uint32_t ph[2][4], pl[2][4];
            {
                const int mrow = wm + (lane & 15);
                const int hf = lane >> 4;
#pragma unroll
                for (int mt = 0; mt < 2; mt++) {
                    int m = mrow + mt * 16;
                    uint32_t ad = sb + AS_K + swz_off(2048, c, m, hf);
                    ldsm4(ph[mt], ad);
                    ldsm4(pl[mt], ad + 8192);
                }
            }
            uint32_t vh[8][2], vl[8][2];
            {
                const int noff = (lane & 7) + ((lane >> 4) & 1) * 8;
                const int hf = (lane >> 3) & 1;
#pragma unroll
                for (int p = 0; p < 4; p++) {
                    int n = wno + p * 16 + noff;
                    uint32_t bd = sb + AS_V + swz_off(4096, c, n, hf);
                    uint32_t r[4];
                    ldsm4(r, bd);
                    vh[2*p][0]=r[0]; vh[2*p][1]=r[1]; vh[2*p+1][0]=r[2]; vh[2*p+1][1]=r[3];
                    ldsm4(r, bd + 16384);
                    vl[2*p][0]=r[0]; vl[2*p][1]=r[1]; vl[2*p+1][0]=r[2]; vl[2*p+1][1]=r[3];
                }
            }
#pragma unroll
            for (int mt = 0; mt < 2; mt++)
#pragma unroll
                for (int nt = 0; nt < 8; nt++) {
                    mma_bf16(o_acc[mt][nt], ph[mt], vh[nt]);
                    mma_bf16(o_acc[mt][nt], ph[mt], vl[nt]);
                    mma_bf16(o_acc[mt][nt], pl[mt], vh[nt]);
                }
        }
        __syncthreads();
    }

    // ---- normalize + store split bf16 (feeds O-projection) ----
#pragma unroll
    for (int mt = 0; mt < 2; mt++) {
        float inv0 = 1.f / l_row[mt][0];
        float inv1 = 1.f / l_row[mt][1];
        int r = qt * 64 + wm + mt * 16 + g;
#pragma unroll
        for (int nt = 0; nt < 8; nt++) {
            int col = h * HD + wno + nt * 8 + tig * 2;
            float v0 = o_acc[mt][nt][0] * inv0, v1 = o_acc[mt][nt][1] * inv0;
            float v2 = o_acc[mt][nt][2] * inv1, v3 = o_acc[mt][nt][3] * inv1;
            __nv_bfloat16 h0,l0,h1,l1,h2,l2,h3,l3;
            split1(v0,h0,l0); split1(v1,h1,l1); split1(v2,h2,l2); split1(v3,h3,l3);
            *(uint32_t*)(ohi + (size_t)r * QD + col)       = pack2(h0,h1);
            *(uint32_t*)(olo + (size_t)r * QD + col)       = pack2(l0,l1);
            *(uint32_t*)(ohi + (size_t)(r + 8) * QD + col) = pack2(h2,h3);
            *(uint32_t*)(olo + (size_t)(r + 8) * QD + col) = pack2(l2,l3);
        }
    }
}

// ---------------------------------------------------------------------------
// Launch
// ---------------------------------------------------------------------------
extern "C" void kernel_launch(void* const* d_in, const int* in_sizes, int n_in,
                              void* d_out, int out_size)
{
    const float* hidden = (const float*)d_in[0];
    // d_in[1] = attention_mask: all-True by construction; causality applied exactly.
    const int*   pos_ids = (const int*)d_in[2];
    const float* Wq = (const float*)d_in[3];
    const float* bq = (const float*)d_in[4];
    const float* Wk = (const float*)d_in[5];
    const float* bk = (const float*)d_in[6];
    const float* Wv = (const float*)d_in[7];
    const float* bv = (const float*)d_in[8];
    const float* Wo = (const float*)d_in[9];
    const float* bo = (const float*)d_in[10];
    float* out = (float*)d_out;

    float *pqkv, *pbqkv;
    __nv_bfloat16 *hh, *hl, *ah, *al;
    __nv_bfloat16 *qh, *ql, *kh, *kl, *vth, *vtl;
    __nv_bfloat16 *wqkvh, *wqkvl, *woh, *wol;
    cudaGetSymbolAddress((void**)&pqkv, g_qkv);
    cudaGetSymbolAddress((void**)&pbqkv, g_bqkv);
    cudaGetSymbolAddress((void**)&hh, g_h_hi);  cudaGetSymbolAddress((void**)&hl, g_h_lo);
    cudaGetSymbolAddress((void**)&ah, g_a_hi);  cudaGetSymbolAddress((void**)&al, g_a_lo);
    cudaGetSymbolAddress((void**)&qh, g_q_hi);  cudaGetSymbolAddress((void**)&ql, g_q_lo);
    cudaGetSymbolAddress((void**)&kh, g_k_hi);  cudaGetSymbolAddress((void**)&kl, g_k_lo);
    cudaGetSymbolAddress((void**)&vth, g_vt_hi); cudaGetSymbolAddress((void**)&vtl, g_vt_lo);
    cudaGetSymbolAddress((void**)&wqkvh, g_wqkv_hi); cudaGetSymbolAddress((void**)&wqkvl, g_wqkv_lo);
    cudaGetSymbolAddress((void**)&woh, g_wo_hi); cudaGetSymbolAddress((void**)&wol, g_wo_lo);

    cudaFuncSetAttribute(gemm_bf16, cudaFuncAttributeMaxDynamicSharedMemorySize, GEMM_SMEM);
    cudaFuncSetAttribute(attn_tc,  cudaFuncAttributeMaxDynamicSharedMemorySize, ATTN_SMEM);

    dim3 blk(256);

    // Weight transpose + bf16 split into fused [q|k|v] buffer, plus Wo
    transpose_split<<<dim3(QD/32,  HID/32), blk>>>(Wq, wqkvh, wqkvl, HID, QD, QD);
    transpose_split<<<dim3(KVD/32, HID/32), blk>>>(Wk, wqkvh + (size_t)QD*HID,
                                                   wqkvl + (size_t)QD*HID, HID, KVD, KVD);
    transpose_split<<<dim3(KVD/32, HID/32), blk>>>(Wv, wqkvh + (size_t)(QD+KVD)*HID,
                                                   wqkvl + (size_t)(QD+KVD)*HID, HID, KVD, KVD);
    transpose_split<<<dim3(QD/32,  HID/32), blk>>>(Wo, woh, wol, QD, HID, HID);
    concat_bias<<<QKVD/256, blk>>>(bq, bk, bv, pbqkv);

    // Activation split for fused QKV projection
    split_f32<<<(SEQ*HID/4 + 255)/256, blk>>>(hidden, hh, hl, SEQ*HID/4);

    // Fused QKV projection (one N=6144 GEMM; grid x = M fast for L2 reuse of B)
    gemm_bf16<<<dim3(SEQ/128, QKVD/128), blk, GEMM_SMEM>>>(hh, hl, wqkvh, wqkvl,
                                                           pbqkv, pqkv, SEQ, QKVD, HID);

    // V transpose+split: V[s][n] (stride QKVD) -> Vt[n][s] hi/lo
    transpose_split<<<dim3(KVD/32, SEQ/32), blk>>>(pqkv + QD + KVD, vth, vtl, SEQ, KVD, QKVD);

    // RoPE -> split bf16 q (scaled) / k
    rope_kernel<<<SEQ, 64>>>(pqkv, pos_ids, qh, ql, kh, kl);

    // Tensor-core causal flash attention (writes split bf16 directly)
    attn_tc<<<dim3(SEQ/64, NHEADS), 128, ATTN_SMEM>>>(qh, ql, kh, kl, vth, vtl, ah, al);

    // Output projection (grid x = M fast)
    gemm_bf16<<<dim3(SEQ/128, HID/128), blk, GEMM_SMEM>>>(ah, al, woh, wol, bo, out, SEQ, HID, QD);
}